// round 16
// baseline (speedup 1.0000x reference)
#include <cuda_runtime.h>
#include <cuda_fp16.h>
#include <math.h>
#include <stdint.h>

#define T_TOK   4096
#define DM      768
#define DE      3072
#define N_EXP   8
#define TOPK    2
#define NSLOT   (T_TOK * TOPK)
#define MAXTILE 72
#define SPLITK  2

// ---------------- scratch ----------------
__device__ int    g_cnt[N_EXP];
__device__ int    g_off[N_EXP + 1];
__device__ int    g_tok[NSLOT];
__device__ float  g_wt[NSLOT];
__device__ int    g_ntiles;
__device__ int2   g_tile[MAXTILE];
__device__ __align__(256) __half g_xH[(size_t)T_TOK * DM];
__device__ __align__(256) __half g_wgH[(size_t)N_EXP * DM * DE];
__device__ __align__(256) __half g_wuH[(size_t)N_EXP * DM * DE];
__device__ __align__(256) __half g_wdH[(size_t)N_EXP * DE * DM];
__device__ __align__(256) __half g_hH[(size_t)(NSLOT + 160) * DE];

// ---------------- helpers ----------------
__device__ __forceinline__ uint32_t smem_u32(const void* p) {
    uint32_t a;
    asm("{ .reg .u64 t; cvta.to.shared.u64 t, %1; cvt.u32.u64 %0, t; }" : "=r"(a) : "l"(p));
    return a;
}
#define CP16(dst, src) asm volatile("cp.async.cg.shared.global [%0], [%1], 16;" :: "r"(dst), "l"(src))
#define CP_COMMIT()    asm volatile("cp.async.commit_group;" ::: "memory")
#define CP_WAIT2()     asm volatile("cp.async.wait_group 2;" ::: "memory")
#define CP_WAIT3()     asm volatile("cp.async.wait_group 3;" ::: "memory")

#define LDSM_X4(r0, r1, r2, r3, a) \
    asm volatile("ldmatrix.sync.aligned.m8n8.x4.shared.b16 {%0,%1,%2,%3}, [%4];" \
                 : "=r"(r0), "=r"(r1), "=r"(r2), "=r"(r3) : "r"(a))
#define LDSM_X4T(r0, r1, r2, r3, a) \
    asm volatile("ldmatrix.sync.aligned.m8n8.x4.trans.shared.b16 {%0,%1,%2,%3}, [%4];" \
                 : "=r"(r0), "=r"(r1), "=r"(r2), "=r"(r3) : "r"(a))

__device__ __forceinline__ void mma_f16(float* c, const uint32_t* a, const uint32_t* b) {
    asm volatile("mma.sync.aligned.m16n8k16.row.col.f32.f16.f16.f32 "
                 "{%0,%1,%2,%3}, {%4,%5,%6,%7}, {%8,%9}, {%0,%1,%2,%3};"
                 : "+f"(c[0]), "+f"(c[1]), "+f"(c[2]), "+f"(c[3])
                 : "r"(a[0]), "r"(a[1]), "r"(a[2]), "r"(a[3]), "r"(b[0]), "r"(b[1]));
}

__device__ __forceinline__ float silu_mul(float g, float u) {
    return __fdividef(g, 1.0f + __expf(-g)) * u;
}

#define A_STRIDE 80
#define B_STRIDE 272
#define A_BYTES  (128 * A_STRIDE)   // 10240
#define B_BYTES  (32 * B_STRIDE)    // 8704

#define NWEL ((size_t)N_EXP * DM * DE)
#define NXEL ((size_t)T_TOK * DM)

// ---------------- routing with duplicate-expert merge ----------------
__global__ __launch_bounds__(1024) void k_route(const int* __restrict__ eidx,
                                                const float* __restrict__ rw) {
    __shared__ int cnt[N_EXP], off[N_EXP], fill[N_EXP];
    const int tid = threadIdx.x;
    if (tid < N_EXP) { cnt[tid] = 0; fill[tid] = 0; }
    __syncthreads();
    int  e0[4], e1[4];
    float w0[4], w1[4];
    #pragma unroll
    for (int j = 0; j < 4; j++) {
        int t = tid + 1024 * j;
        int2  ee = *(const int2*)(eidx + 2 * t);
        float2 ww = *(const float2*)(rw + 2 * t);
        e0[j] = ee.x; e1[j] = ee.y; w0[j] = ww.x; w1[j] = ww.y;
        atomicAdd(&cnt[e0[j]], 1);
        if (e1[j] != e0[j]) atomicAdd(&cnt[e1[j]], 1);
    }
    __syncthreads();
    if (tid == 0) {
        int a = 0, nt = 0;
        for (int e = 0; e < N_EXP; e++) {
            off[e] = a; g_off[e] = a; g_cnt[e] = cnt[e];
            for (int rb = 0; rb < cnt[e]; rb += 128) g_tile[nt++] = make_int2(e, rb);
            a += cnt[e];
        }
        g_off[N_EXP] = a;
        g_ntiles = nt;
    }
    __syncthreads();
    #pragma unroll
    for (int j = 0; j < 4; j++) {
        int t = tid + 1024 * j;
        if (e1[j] == e0[j]) {
            int p = off[e0[j]] + atomicAdd(&fill[e0[j]], 1);
            g_tok[p] = t; g_wt[p] = w0[j] + w1[j];
        } else {
            int p0 = off[e0[j]] + atomicAdd(&fill[e0[j]], 1);
            g_tok[p0] = t; g_wt[p0] = w0[j];
            int p1 = off[e1[j]] + atomicAdd(&fill[e1[j]], 1);
            g_tok[p1] = t; g_wt[p1] = w1[j];
        }
    }
}

// ---------------- convert + zero: 512 threads/block, 8192 float4/block ------
#define WBLK 576    // NWEL/4/8192
#define XBLK 96     // NXEL/4/8192

__global__ __launch_bounds__(512) void k_cvt_zero(const float* __restrict__ wg,
                                                  const float* __restrict__ wu,
                                                  const float* __restrict__ wd,
                                                  const float* __restrict__ x,
                                                  float* __restrict__ out) {
    int b = blockIdx.x;
    const int tid = threadIdx.x;

    const float* s; __half* d;
    if (b < WBLK)            { s = wg; d = g_wgH; }
    else if (b < 2 * WBLK)   { s = wu; d = g_wuH; b -= WBLK; }
    else if (b < 3 * WBLK)   { s = wd; d = g_wdH; b -= 2 * WBLK; }
    else if (b < 3 * WBLK + XBLK) { s = x; d = g_xH; b -= 3 * WBLK; }
    else {
        b -= 3 * WBLK + XBLK;
        size_t base = ((size_t)b * 8192 + tid) * 4;
        #pragma unroll
        for (int j = 0; j < 16; j++)
            *(float4*)(out + base + (size_t)j * 2048) = make_float4(0.f, 0.f, 0.f, 0.f);
        return;
    }
    size_t base = ((size_t)b * 8192 + tid) * 4;
    #pragma unroll
    for (int j = 0; j < 16; j++) {
        size_t i = base + (size_t)j * 2048;
        float4 v = *(const float4*)(s + i);
        *(__half2*)(d + i)     = __floats2half2_rn(v.x, v.y);
        *(__half2*)(d + i + 2) = __floats2half2_rn(v.z, v.w);
    }
}

// ===========================================================================
// GEMM1: h = silu(x Wg) * (x Wu) — 512 threads, 4x4 warps, 5-stage cp.async
// ===========================================================================
#define STG1 (A_BYTES + 2 * B_BYTES)   // 27648
#define NSTG1 5
#define S1_SMEM (NSTG1 * STG1)         // 138240
#define NS1 24

__global__ __launch_bounds__(512) void k_mma1() {
    if (blockIdx.y >= (unsigned)g_ntiles) return;
    const int2 te = g_tile[blockIdx.y];
    const int e = te.x, row0 = te.y;
    const int cnt = g_cnt[e];
    const int base = g_off[e];
    const int col0 = blockIdx.x * 128;

    extern __shared__ char sm[];
    const uint32_t sa = smem_u32(sm);

    const int tid = threadIdx.x;
    const int wid = tid >> 5, lid = tid & 31;
    const int wm = wid >> 2, wn = wid & 3;
    const int g = lid >> 2, t = lid & 3;
    const int lidlo = lid & 15, lidhi = lid >> 4;

    const int ar = tid >> 2, ac = tid & 3;
    const int br = tid >> 4, bc = tid & 15;
    int rr = row0 + ar;
    int idx = base + (rr < cnt ? rr : cnt - 1);
    const char* pA = (const char*)(g_xH + (size_t)g_tok[idx] * DM) + ac * 16;
    const char* pG = (const char*)(g_wgH + ((size_t)e * DM + br) * DE + col0) + bc * 16;
    const char* pU = (const char*)(g_wuH + ((size_t)e * DM + br) * DE + col0) + bc * 16;
    const uint32_t aoff = (uint32_t)(ar * A_STRIDE + ac * 16);
    const uint32_t boff = (uint32_t)(br * B_STRIDE + bc * 16);
    const size_t bAdv = (size_t)32 * DE * 2;

#define LOAD1(buf) do {                                                        \
        uint32_t ab = sa + (uint32_t)((buf) * STG1);                           \
        uint32_t gb = ab + A_BYTES, ub = gb + B_BYTES;                         \
        CP16(ab + aoff, pA); pA += 64;                                         \
        CP16(gb + boff, pG); CP16(ub + boff, pU);                              \
        pG += bAdv; pU += bAdv; } while (0)

    float accG[2][4][4] = {}, accU[2][4][4] = {};

    LOAD1(0); CP_COMMIT();
    LOAD1(1); CP_COMMIT();
    LOAD1(2); CP_COMMIT();
    LOAD1(3); CP_COMMIT();

    for (int s = 0; s < NS1; s++) {
        CP_WAIT3();
        __syncthreads();
        if (s + 4 < NS1) LOAD1((s + 4) % NSTG1);
        CP_COMMIT();

        const uint32_t ab = sa + (uint32_t)((s % NSTG1) * STG1);
        const uint32_t gb = ab + A_BYTES, ub = gb + B_BYTES;

        #pragma unroll
        for (int kst = 0; kst < 2; kst++) {
            uint32_t a[2][4], bg[4][2], bu[4][2];
            #pragma unroll
            for (int mi = 0; mi < 2; mi++) {
                uint32_t addr = ab + (uint32_t)((wm * 32 + mi * 16 + lidlo) * A_STRIDE
                                                + (kst * 16 + 8 * lidhi) * 2);
                LDSM_X4(a[mi][0], a[mi][1], a[mi][2], a[mi][3], addr);
            }
            #pragma unroll
            for (int nh = 0; nh < 2; nh++) {
                uint32_t co = (uint32_t)((wn * 32 + nh * 16 + 8 * lidhi) * 2);
                uint32_t ro = (uint32_t)((kst * 16 + lidlo) * B_STRIDE);
                LDSM_X4T(bg[2 * nh][0], bg[2 * nh][1], bg[2 * nh + 1][0], bg[2 * nh + 1][1],
                         gb + ro + co);
                LDSM_X4T(bu[2 * nh][0], bu[2 * nh][1], bu[2 * nh + 1][0], bu[2 * nh + 1][1],
                         ub + ro + co);
            }
            #pragma unroll
            for (int mi = 0; mi < 2; mi++)
                #pragma unroll
                for (int ni = 0; ni < 4; ni++) {
                    mma_f16(accG[mi][ni], a[mi], bg[ni]);
                    mma_f16(accU[mi][ni], a[mi], bu[ni]);
                }
        }
    }

    #pragma unroll
    for (int mi = 0; mi < 2; mi++) {
        #pragma unroll
        for (int hh = 0; hh < 2; hh++) {
            int r = row0 + wm * 32 + mi * 16 + g + 8 * hh;
            if (r >= cnt) continue;
            __half* hrow = g_hH + (size_t)(base + r) * DE + col0;
            #pragma unroll
            for (int ni = 0; ni < 4; ni++) {
                int col = wn * 32 + ni * 8 + 2 * t;
                float h0 = silu_mul(accG[mi][ni][2 * hh],     accU[mi][ni][2 * hh]);
                float h1 = silu_mul(accG[mi][ni][2 * hh + 1], accU[mi][ni][2 * hh + 1]);
                *(__half2*)(hrow + col) = __floats2half2_rn(h0, h1);
            }
        }
    }
}

// ===========================================================================
// GEMM2: out += (h Wd) * wt — split-K=2 (champion exact)
// ===========================================================================
#define STG2 (A_BYTES + B_BYTES)    // 18944
#define S2_SMEM (4 * STG2)          // 75776
#define NS2H (96 / SPLITK)          // 48

__global__ __launch_bounds__(256) void k_mma2(float* __restrict__ out) {
    if (blockIdx.y >= (unsigned)g_ntiles) return;
    const int2 te = g_tile[blockIdx.y];
    const int e = te.x, row0 = te.y;
    const int cnt = g_cnt[e];
    const int base = g_off[e];
    const int col0 = blockIdx.x * 128;
    const int k0  = blockIdx.z * (NS2H * 32);

    extern __shared__ char sm[];
    const uint32_t sa = smem_u32(sm);

    const int tid = threadIdx.x;
    const int wid = tid >> 5, lid = tid & 31;
    const int wm = wid >> 2, wn = wid & 3;
    const int g = lid >> 2, t = lid & 3;
    const int lidlo = lid & 15, lidhi = lid >> 4;

    uint32_t aoff[2], boff[2];
    const char* pA[2]; const char* pB[2];
    #pragma unroll
    for (int j = 0; j < 2; j++) {
        int task = tid + 256 * j;
        int ar = task >> 2, ac = task & 3;
        pA[j] = (const char*)(g_hH + (size_t)(base + row0 + ar) * DE + k0) + ac * 16;
        aoff[j] = (uint32_t)(ar * A_STRIDE + ac * 16);
        int br = task >> 4, bc = task & 15;
        pB[j] = (const char*)(g_wdH + ((size_t)e * DE + k0 + br) * DM + col0) + bc * 16;
        boff[j] = (uint32_t)(br * B_STRIDE + bc * 16);
    }
    const size_t bAdv = (size_t)32 * DM * 2;

#define LOAD2(buf) do {                                                        \
        uint32_t ab = sa + (uint32_t)((buf) * STG2);                           \
        uint32_t bb = ab + A_BYTES;                                            \
        _Pragma("unroll") for (int j = 0; j < 2; j++) {                        \
            CP16(ab + aoff[j], pA[j]); pA[j] += 64;                            \
            CP16(bb + boff[j], pB[j]); pB[j] += bAdv; } } while (0)

    float acc[4][4][4] = {};

    LOAD2(0); CP_COMMIT();
    LOAD2(1); CP_COMMIT();
    LOAD2(2); CP_COMMIT();

    for (int s = 0; s < NS2H; s++) {
        CP_WAIT2();
        __syncthreads();
        if (s + 3 < NS2H) LOAD2((s + 3) & 3);
        CP_COMMIT();

        const uint32_t ab = sa + (uint32_t)((s & 3) * STG2);
        const uint32_t bb = ab + A_BYTES;

        #pragma unroll
        for (int kst = 0; kst < 2; kst++) {
            uint32_t a[4][4], bf[4][2];
            #pragma unroll
            for (int mi = 0; mi < 4; mi++) {
                uint32_t addr = ab + (uint32_t)((wm * 64 + mi * 16 + lidlo) * A_STRIDE
                                                + (kst * 16 + 8 * lidhi) * 2);
                LDSM_X4(a[mi][0], a[mi][1], a[mi][2], a[mi][3], addr);
            }
            #pragma unroll
            for (int nh = 0; nh < 2; nh++) {
                uint32_t co = (uint32_t)((wn * 32 + nh * 16 + 8 * lidhi) * 2);
                uint32_t ro = (uint32_t)((kst * 16 + lidlo) * B_STRIDE);
                LDSM_X4T(bf[2 * nh][0], bf[2 * nh][1], bf[2 * nh + 1][0], bf[2 * nh + 1][1],
                         bb + ro + co);
            }
            #pragma unroll
            for (int mi = 0; mi < 4; mi++)
                #pragma unroll
                for (int ni = 0; ni < 4; ni++)
                    mma_f16(acc[mi][ni], a[mi], bf[ni]);
        }
    }

    #pragma unroll
    for (int mi = 0; mi < 4; mi++) {
        #pragma unroll
        for (int hh = 0; hh < 2; hh++) {
            int r = row0 + wm * 64 + mi * 16 + g + 8 * hh;
            if (r >= cnt) continue;
            float w = g_wt[base + r];
            float* orow = out + (size_t)g_tok[base + r] * DM + col0;
            #pragma unroll
            for (int ni = 0; ni < 4; ni++) {
                int col = wn * 32 + ni * 8 + 2 * t;
                atomicAdd(&orow[col],     acc[mi][ni][2 * hh]     * w);
                atomicAdd(&orow[col + 1], acc[mi][ni][2 * hh + 1] * w);
            }
        }
    }
}

// ---------------------------------------------------------------------------
extern "C" void kernel_launch(void* const* d_in, const int* in_sizes, int n_in,
                              void* d_out, int out_size) {
    const float* x  = (const float*)d_in[0];
    const float* rw = (const float*)d_in[1];
    const float* wg = (const float*)d_in[2];
    const float* wu = (const float*)d_in[3];
    const float* wd = (const float*)d_in[4];
    const int*   ei = (const int*)d_in[5];
    float* out = (float*)d_out;

    static bool attr_done = false;
    if (!attr_done) {
        cudaFuncSetAttribute(k_mma1, cudaFuncAttributeMaxDynamicSharedMemorySize, S1_SMEM);
        cudaFuncSetAttribute(k_mma2, cudaFuncAttributeMaxDynamicSharedMemorySize, S2_SMEM);
        attr_done = true;
    }

    k_route<<<1, 1024>>>(ei, rw);
    k_cvt_zero<<<3 * WBLK + 2 * XBLK, 512>>>(wg, wu, wd, x, out);

    dim3 g1(DE / 128, MAXTILE);           // 24 x 72
    k_mma1<<<g1, 512, S1_SMEM>>>();

    dim3 g2(DM / 128, MAXTILE, SPLITK);   // 6 x 72 x 2
    k_mma2<<<g2, 256, S2_SMEM>>>(out);
}

// round 17
// speedup vs baseline: 1.0654x; 1.0654x over previous
#include <cuda_runtime.h>
#include <cuda_fp16.h>
#include <math.h>
#include <stdint.h>

#define T_TOK   4096
#define DM      768
#define DE      3072
#define N_EXP   8
#define TOPK    2
#define NSLOT   (T_TOK * TOPK)
#define MAXTILE 72
#define SPLITK  2

// ---------------- scratch ----------------
__device__ int    g_cnt[N_EXP];
__device__ int    g_off[N_EXP + 1];
__device__ int    g_tok[NSLOT];
__device__ float  g_wt[NSLOT];
__device__ int    g_ntiles;
__device__ int2   g_tile[MAXTILE];
__device__ __align__(256) __half g_xH[(size_t)T_TOK * DM];
__device__ __align__(256) __half g_wgH[(size_t)N_EXP * DM * DE];
__device__ __align__(256) __half g_wuH[(size_t)N_EXP * DM * DE];
__device__ __align__(256) __half g_wdH[(size_t)N_EXP * DE * DM];
__device__ __align__(256) __half g_hH[(size_t)(NSLOT + 160) * DE];

// ---------------- helpers ----------------
__device__ __forceinline__ uint32_t smem_u32(const void* p) {
    uint32_t a;
    asm("{ .reg .u64 t; cvta.to.shared.u64 t, %1; cvt.u32.u64 %0, t; }" : "=r"(a) : "l"(p));
    return a;
}
#define CP16(dst, src) asm volatile("cp.async.cg.shared.global [%0], [%1], 16;" :: "r"(dst), "l"(src))
#define CP_COMMIT()    asm volatile("cp.async.commit_group;" ::: "memory")
#define CP_WAIT2()     asm volatile("cp.async.wait_group 2;" ::: "memory")

#define LDSM_X4(r0, r1, r2, r3, a) \
    asm volatile("ldmatrix.sync.aligned.m8n8.x4.shared.b16 {%0,%1,%2,%3}, [%4];" \
                 : "=r"(r0), "=r"(r1), "=r"(r2), "=r"(r3) : "r"(a))
#define LDSM_X4T(r0, r1, r2, r3, a) \
    asm volatile("ldmatrix.sync.aligned.m8n8.x4.trans.shared.b16 {%0,%1,%2,%3}, [%4];" \
                 : "=r"(r0), "=r"(r1), "=r"(r2), "=r"(r3) : "r"(a))

__device__ __forceinline__ void mma_f16(float* c, const uint32_t* a, const uint32_t* b) {
    asm volatile("mma.sync.aligned.m16n8k16.row.col.f32.f16.f16.f32 "
                 "{%0,%1,%2,%3}, {%4,%5,%6,%7}, {%8,%9}, {%0,%1,%2,%3};"
                 : "+f"(c[0]), "+f"(c[1]), "+f"(c[2]), "+f"(c[3])
                 : "r"(a[0]), "r"(a[1]), "r"(a[2]), "r"(a[3]), "r"(b[0]), "r"(b[1]));
}

__device__ __forceinline__ float silu_mul(float g, float u) {
    return __fdividef(g, 1.0f + __expf(-g)) * u;
}

#define A_STRIDE 80
#define B_STRIDE 272
#define A_BYTES  (128 * A_STRIDE)   // 10240
#define B_BYTES  (32 * B_STRIDE)    // 8704

#define NWEL ((size_t)N_EXP * DM * DE)
#define NXEL ((size_t)T_TOK * DM)

// ---------------- routing with duplicate-expert merge ----------------
__global__ __launch_bounds__(1024) void k_route(const int* __restrict__ eidx,
                                                const float* __restrict__ rw) {
    __shared__ int cnt[N_EXP], off[N_EXP], fill[N_EXP];
    const int tid = threadIdx.x;
    if (tid < N_EXP) { cnt[tid] = 0; fill[tid] = 0; }
    __syncthreads();
    int  e0[4], e1[4];
    float w0[4], w1[4];
    #pragma unroll
    for (int j = 0; j < 4; j++) {
        int t = tid + 1024 * j;
        int2  ee = *(const int2*)(eidx + 2 * t);
        float2 ww = *(const float2*)(rw + 2 * t);
        e0[j] = ee.x; e1[j] = ee.y; w0[j] = ww.x; w1[j] = ww.y;
        atomicAdd(&cnt[e0[j]], 1);
        if (e1[j] != e0[j]) atomicAdd(&cnt[e1[j]], 1);
    }
    __syncthreads();
    if (tid == 0) {
        int a = 0, nt = 0;
        for (int e = 0; e < N_EXP; e++) {
            off[e] = a; g_off[e] = a; g_cnt[e] = cnt[e];
            for (int rb = 0; rb < cnt[e]; rb += 128) g_tile[nt++] = make_int2(e, rb);
            a += cnt[e];
        }
        g_off[N_EXP] = a;
        g_ntiles = nt;
    }
    __syncthreads();
    #pragma unroll
    for (int j = 0; j < 4; j++) {
        int t = tid + 1024 * j;
        if (e1[j] == e0[j]) {
            int p = off[e0[j]] + atomicAdd(&fill[e0[j]], 1);
            g_tok[p] = t; g_wt[p] = w0[j] + w1[j];
        } else {
            int p0 = off[e0[j]] + atomicAdd(&fill[e0[j]], 1);
            g_tok[p0] = t; g_wt[p0] = w0[j];
            int p1 = off[e1[j]] + atomicAdd(&fill[e1[j]], 1);
            g_tok[p1] = t; g_wt[p1] = w1[j];
        }
    }
}

// ---------------- convert + zero ----------------
#define WBLK 1152
#define XBLK 192

__global__ __launch_bounds__(256) void k_cvt_zero(const float* __restrict__ wg,
                                                  const float* __restrict__ wu,
                                                  const float* __restrict__ wd,
                                                  const float* __restrict__ x,
                                                  float* __restrict__ out) {
    int b = blockIdx.x;
    const int tid = threadIdx.x;

    const float* s; __half* d;
    if (b < WBLK)            { s = wg; d = g_wgH; }
    else if (b < 2 * WBLK)   { s = wu; d = g_wuH; b -= WBLK; }
    else if (b < 3 * WBLK)   { s = wd; d = g_wdH; b -= 2 * WBLK; }
    else if (b < 3 * WBLK + XBLK) { s = x; d = g_xH; b -= 3 * WBLK; }
    else {
        b -= 3 * WBLK + XBLK;
        size_t base = ((size_t)b * 4096 + tid) * 4;
        #pragma unroll
        for (int j = 0; j < 16; j++)
            *(float4*)(out + base + (size_t)j * 1024) = make_float4(0.f, 0.f, 0.f, 0.f);
        return;
    }
    size_t base = ((size_t)b * 4096 + tid) * 4;
    #pragma unroll
    for (int j = 0; j < 16; j++) {
        size_t i = base + (size_t)j * 1024;
        float4 v = *(const float4*)(s + i);
        *(__half2*)(d + i)     = __floats2half2_rn(v.x, v.y);
        *(__half2*)(d + i + 2) = __floats2half2_rn(v.z, v.w);
    }
}

// ===========================================================================
// GEMM1: h = silu(x Wg) * (x Wu) — 512 threads, 4x4 warp grid, 4-stage pipeline
// ===========================================================================
#define STG1 (A_BYTES + 2 * B_BYTES)   // 27648
#define S1_SMEM (4 * STG1)             // 110592
#define NS1 24

__global__ __launch_bounds__(512) void k_mma1() {
    if (blockIdx.y >= (unsigned)g_ntiles) return;
    const int2 te = g_tile[blockIdx.y];
    const int e = te.x, row0 = te.y;
    const int cnt = g_cnt[e];
    const int base = g_off[e];
    const int col0 = blockIdx.x * 128;

    extern __shared__ char sm[];
    const uint32_t sa = smem_u32(sm);

    const int tid = threadIdx.x;
    const int wid = tid >> 5, lid = tid & 31;
    const int wm = wid >> 2, wn = wid & 3;
    const int g = lid >> 2, t = lid & 3;
    const int lidlo = lid & 15, lidhi = lid >> 4;

    const int ar = tid >> 2, ac = tid & 3;
    const int br = tid >> 4, bc = tid & 15;
    int rr = row0 + ar;
    int idx = base + (rr < cnt ? rr : cnt - 1);
    const char* pA = (const char*)(g_xH + (size_t)g_tok[idx] * DM) + ac * 16;
    const char* pG = (const char*)(g_wgH + ((size_t)e * DM + br) * DE + col0) + bc * 16;
    const char* pU = (const char*)(g_wuH + ((size_t)e * DM + br) * DE + col0) + bc * 16;
    const uint32_t aoff = (uint32_t)(ar * A_STRIDE + ac * 16);
    const uint32_t boff = (uint32_t)(br * B_STRIDE + bc * 16);
    const size_t bAdv = (size_t)32 * DE * 2;

#define LOAD1(buf) do {                                                        \
        uint32_t ab = sa + (uint32_t)((buf) * STG1);                           \
        uint32_t gb = ab + A_BYTES, ub = gb + B_BYTES;                         \
        CP16(ab + aoff, pA); pA += 64;                                         \
        CP16(gb + boff, pG); CP16(ub + boff, pU);                              \
        pG += bAdv; pU += bAdv; } while (0)

    float accG[2][4][4] = {}, accU[2][4][4] = {};

    LOAD1(0); CP_COMMIT();
    LOAD1(1); CP_COMMIT();
    LOAD1(2); CP_COMMIT();

    for (int s = 0; s < NS1; s++) {
        CP_WAIT2();
        __syncthreads();
        if (s + 3 < NS1) LOAD1((s + 3) & 3);
        CP_COMMIT();

        const uint32_t ab = sa + (uint32_t)((s & 3) * STG1);
        const uint32_t gb = ab + A_BYTES, ub = gb + B_BYTES;

        #pragma unroll
        for (int kst = 0; kst < 2; kst++) {
            uint32_t a[2][4], bg[4][2], bu[4][2];
            #pragma unroll
            for (int mi = 0; mi < 2; mi++) {
                uint32_t addr = ab + (uint32_t)((wm * 32 + mi * 16 + lidlo) * A_STRIDE
                                                + (kst * 16 + 8 * lidhi) * 2);
                LDSM_X4(a[mi][0], a[mi][1], a[mi][2], a[mi][3], addr);
            }
            #pragma unroll
            for (int nh = 0; nh < 2; nh++) {
                uint32_t co = (uint32_t)((wn * 32 + nh * 16 + 8 * lidhi) * 2);
                uint32_t ro = (uint32_t)((kst * 16 + lidlo) * B_STRIDE);
                LDSM_X4T(bg[2 * nh][0], bg[2 * nh][1], bg[2 * nh + 1][0], bg[2 * nh + 1][1],
                         gb + ro + co);
                LDSM_X4T(bu[2 * nh][0], bu[2 * nh][1], bu[2 * nh + 1][0], bu[2 * nh + 1][1],
                         ub + ro + co);
            }
            #pragma unroll
            for (int mi = 0; mi < 2; mi++)
                #pragma unroll
                for (int ni = 0; ni < 4; ni++) {
                    mma_f16(accG[mi][ni], a[mi], bg[ni]);
                    mma_f16(accU[mi][ni], a[mi], bu[ni]);
                }
        }
    }

    #pragma unroll
    for (int mi = 0; mi < 2; mi++) {
        #pragma unroll
        for (int hh = 0; hh < 2; hh++) {
            int r = row0 + wm * 32 + mi * 16 + g + 8 * hh;
            if (r >= cnt) continue;
            __half* hrow = g_hH + (size_t)(base + r) * DE + col0;
            #pragma unroll
            for (int ni = 0; ni < 4; ni++) {
                int col = wn * 32 + ni * 8 + 2 * t;
                float h0 = silu_mul(accG[mi][ni][2 * hh],     accU[mi][ni][2 * hh]);
                float h1 = silu_mul(accG[mi][ni][2 * hh + 1], accU[mi][ni][2 * hh + 1]);
                *(__half2*)(hrow + col) = __floats2half2_rn(h0, h1);
            }
        }
    }
}

// ===========================================================================
// GEMM2: out += (h Wd) * wt — split-K=2
// ===========================================================================
#define STG2 (A_BYTES + B_BYTES)    // 18944
#define S2_SMEM (4 * STG2)          // 75776
#define NS2H (96 / SPLITK)          // 48

__global__ __launch_bounds__(256) void k_mma2(float* __restrict__ out) {
    if (blockIdx.y >= (unsigned)g_ntiles) return;
    const int2 te = g_tile[blockIdx.y];
    const int e = te.x, row0 = te.y;
    const int cnt = g_cnt[e];
    const int base = g_off[e];
    const int col0 = blockIdx.x * 128;
    const int k0  = blockIdx.z * (NS2H * 32);

    extern __shared__ char sm[];
    const uint32_t sa = smem_u32(sm);

    const int tid = threadIdx.x;
    const int wid = tid >> 5, lid = tid & 31;
    const int wm = wid >> 2, wn = wid & 3;
    const int g = lid >> 2, t = lid & 3;
    const int lidlo = lid & 15, lidhi = lid >> 4;

    uint32_t aoff[2], boff[2];
    const char* pA[2]; const char* pB[2];
    #pragma unroll
    for (int j = 0; j < 2; j++) {
        int task = tid + 256 * j;
        int ar = task >> 2, ac = task & 3;
        pA[j] = (const char*)(g_hH + (size_t)(base + row0 + ar) * DE + k0) + ac * 16;
        aoff[j] = (uint32_t)(ar * A_STRIDE + ac * 16);
        int br = task >> 4, bc = task & 15;
        pB[j] = (const char*)(g_wdH + ((size_t)e * DE + k0 + br) * DM + col0) + bc * 16;
        boff[j] = (uint32_t)(br * B_STRIDE + bc * 16);
    }
    const size_t bAdv = (size_t)32 * DM * 2;

#define LOAD2(buf) do {                                                        \
        uint32_t ab = sa + (uint32_t)((buf) * STG2);                           \
        uint32_t bb = ab + A_BYTES;                                            \
        _Pragma("unroll") for (int j = 0; j < 2; j++) {                        \
            CP16(ab + aoff[j], pA[j]); pA[j] += 64;                            \
            CP16(bb + boff[j], pB[j]); pB[j] += bAdv; } } while (0)

    float acc[4][4][4] = {};

    LOAD2(0); CP_COMMIT();
    LOAD2(1); CP_COMMIT();
    LOAD2(2); CP_COMMIT();

    for (int s = 0; s < NS2H; s++) {
        CP_WAIT2();
        __syncthreads();
        if (s + 3 < NS2H) LOAD2((s + 3) & 3);
        CP_COMMIT();

        const uint32_t ab = sa + (uint32_t)((s & 3) * STG2);
        const uint32_t bb = ab + A_BYTES;

        #pragma unroll
        for (int kst = 0; kst < 2; kst++) {
            uint32_t a[4][4], bf[4][2];
            #pragma unroll
            for (int mi = 0; mi < 4; mi++) {
                uint32_t addr = ab + (uint32_t)((wm * 64 + mi * 16 + lidlo) * A_STRIDE
                                                + (kst * 16 + 8 * lidhi) * 2);
                LDSM_X4(a[mi][0], a[mi][1], a[mi][2], a[mi][3], addr);
            }
            #pragma unroll
            for (int nh = 0; nh < 2; nh++) {
                uint32_t co = (uint32_t)((wn * 32 + nh * 16 + 8 * lidhi) * 2);
                uint32_t ro = (uint32_t)((kst * 16 + lidlo) * B_STRIDE);
                LDSM_X4T(bf[2 * nh][0], bf[2 * nh][1], bf[2 * nh + 1][0], bf[2 * nh + 1][1],
                         bb + ro + co);
            }
            #pragma unroll
            for (int mi = 0; mi < 4; mi++)
                #pragma unroll
                for (int ni = 0; ni < 4; ni++)
                    mma_f16(acc[mi][ni], a[mi], bf[ni]);
        }
    }

    #pragma unroll
    for (int mi = 0; mi < 4; mi++) {
        #pragma unroll
        for (int hh = 0; hh < 2; hh++) {
            int r = row0 + wm * 64 + mi * 16 + g + 8 * hh;
            if (r >= cnt) continue;
            float w = g_wt[base + r];
            float* orow = out + (size_t)g_tok[base + r] * DM + col0;
            #pragma unroll
            for (int ni = 0; ni < 4; ni++) {
                int col = wn * 32 + ni * 8 + 2 * t;
                atomicAdd(&orow[col],     acc[mi][ni][2 * hh]     * w);
                atomicAdd(&orow[col + 1], acc[mi][ni][2 * hh + 1] * w);
            }
        }
    }
}

// ---------------------------------------------------------------------------
extern "C" void kernel_launch(void* const* d_in, const int* in_sizes, int n_in,
                              void* d_out, int out_size) {
    const float* x  = (const float*)d_in[0];
    const float* rw = (const float*)d_in[1];
    const float* wg = (const float*)d_in[2];
    const float* wu = (const float*)d_in[3];
    const float* wd = (const float*)d_in[4];
    const int*   ei = (const int*)d_in[5];
    float* out = (float*)d_out;

    static bool attr_done = false;
    if (!attr_done) {
        cudaFuncSetAttribute(k_mma1, cudaFuncAttributeMaxDynamicSharedMemorySize, S1_SMEM);
        cudaFuncSetAttribute(k_mma2, cudaFuncAttributeMaxDynamicSharedMemorySize, S2_SMEM);
        attr_done = true;
    }

    k_route<<<1, 1024>>>(ei, rw);
    k_cvt_zero<<<3 * WBLK + 2 * XBLK, 256>>>(wg, wu, wd, x, out);

    dim3 g1(DE / 128, MAXTILE);           // 24 x 72
    k_mma1<<<g1, 512, S1_SMEM>>>();

    dim3 g2(DM / 128, MAXTILE, SPLITK);   // 6 x 72 x 2
    k_mma2<<<g2, 256, S2_SMEM>>>(out);
}